// round 15
// baseline (speedup 1.0000x reference)
#include <cuda_runtime.h>
#include <cuda.h>
#include <cuda_bf16.h>
#include <math.h>
#include <stdint.h>

#define T_  512
#define B_  256
#define I_  512
#define H_  1024
#define N3  3072
#define M_  (T_ * B_)
#define NW  2048                     // rows of interleaved Wcat (c||a per 32-col block)

#if !defined(__CUDA_ARCH__) || defined(__CUDA_ARCH_FEAT_SM103_ALL) || defined(__CUDA_ARCH_FEAT_SM100_ALL) || defined(__CUDA_ARCH_FEAT_SM101_ALL)
#define TC_OK 1
#else
#define TC_OK 0
#endif

// ---------------- device scratch -----------------------
__device__ float         g_xall[(size_t)M_ * N3];
__device__ __nv_bfloat16 g_Whi[(size_t)NW * H_];
__device__ __nv_bfloat16 g_Wlo[(size_t)NW * H_];
__device__ __nv_bfloat16 g_hhi[2][(size_t)B_ * H_];
__device__ __nv_bfloat16 g_hlo[2][(size_t)B_ * H_];

// ---------------- PTX helpers ----------------------------------------------
__device__ __forceinline__ uint32_t smem_u32(const void* p) {
    uint32_t a;
    asm("{ .reg .u64 t; cvta.to.shared.u64 t, %1; cvt.u32.u64 %0, t; }" : "=r"(a) : "l"(p));
    return a;
}
__device__ __forceinline__ void mbar_init(uint32_t m, uint32_t cnt) {
    asm volatile("mbarrier.init.shared.b64 [%0], %1;" :: "r"(m), "r"(cnt) : "memory");
}
__device__ __forceinline__ void mbar_inval(uint32_t m) {
    asm volatile("mbarrier.inval.shared.b64 [%0];" :: "r"(m) : "memory");
}
__device__ __forceinline__ void mbar_wait(uint32_t m, uint32_t parity) {
    asm volatile(
        "{\n\t.reg .pred P;\n"
        "W%=:\n\t"
        "mbarrier.try_wait.parity.acquire.cta.shared::cta.b64 P, [%0], %1, 0x989680;\n\t"
        "@P bra D%=;\n\t"
        "bra W%=;\n"
        "D%=:\n\t}"
        :: "r"(m), "r"(parity) : "memory");
}
__device__ __forceinline__ void mbar_expect_tx(uint32_t m, uint32_t bytes) {
    asm volatile("mbarrier.arrive.expect_tx.shared.b64 _, [%0], %1;"
                 :: "r"(m), "r"(bytes) : "memory");
}
__device__ __forceinline__ void tma2d(uint32_t smem, const CUtensorMap* map,
                                      int x, int y, uint32_t mbar) {
    asm volatile(
        "cp.async.bulk.tensor.2d.shared::cta.global.tile.mbarrier::complete_tx::bytes "
        "[%0], [%1, {%2, %3}], [%4];"
        :: "r"(smem), "l"(map), "r"(x), "r"(y), "r"(mbar) : "memory");
}

#if TC_OK
__device__ __forceinline__ void tmem_alloc(uint32_t dst_smem, uint32_t ncols) {
    asm volatile("tcgen05.alloc.cta_group::1.sync.aligned.shared::cta.b32 [%0], %1;"
                 :: "r"(dst_smem), "r"(ncols) : "memory");
}
__device__ __forceinline__ void tmem_dealloc(uint32_t tmem, uint32_t ncols) {
    asm volatile("tcgen05.dealloc.cta_group::1.sync.aligned.b32 %0, %1;" :: "r"(tmem), "r"(ncols));
}
__device__ __forceinline__ void tmem_relinquish() {
    asm volatile("tcgen05.relinquish_alloc_permit.cta_group::1.sync.aligned;");
}
__device__ __forceinline__ void tc_commit(uint32_t m) {
    asm volatile("tcgen05.commit.cta_group::1.mbarrier::arrive::one.shared::cluster.b64 [%0];"
                 :: "r"(m) : "memory");
}
__device__ __forceinline__ void tc_fence_after() {
    asm volatile("tcgen05.fence::after_thread_sync;" ::: "memory");
}
__device__ __forceinline__ void tc_fence_before() {
    asm volatile("tcgen05.fence::before_thread_sync;" ::: "memory");
}
__device__ __forceinline__ void tc_wait_ld() {
    asm volatile("tcgen05.wait::ld.sync.aligned;" ::: "memory");
}
__device__ __forceinline__ void mma_f16_ss(uint32_t d, uint64_t ad, uint64_t bd,
                                           uint32_t idesc, uint32_t en) {
    asm volatile(
        "{\n\t.reg .pred p;\n\t"
        "setp.ne.u32 p, %4, 0;\n\t"
        "tcgen05.mma.cta_group::1.kind::f16 [%0], %1, %2, %3, {%5, %5, %5, %5}, p;\n\t}"
        :: "r"(d), "l"(ad), "l"(bd), "r"(idesc), "r"(en), "r"(0u) : "memory");
}
__device__ __forceinline__ void tmem_ld16(uint32_t* r, uint32_t addr) {
    asm volatile(
        "tcgen05.ld.sync.aligned.32x32b.x16.b32 "
        "{%0, %1, %2, %3, %4, %5, %6, %7, "
        " %8, %9, %10, %11, %12, %13, %14, %15}, [%16];"
        : "=r"(r[0]), "=r"(r[1]), "=r"(r[2]), "=r"(r[3]),
          "=r"(r[4]), "=r"(r[5]), "=r"(r[6]), "=r"(r[7]),
          "=r"(r[8]), "=r"(r[9]), "=r"(r[10]), "=r"(r[11]),
          "=r"(r[12]), "=r"(r[13]), "=r"(r[14]), "=r"(r[15])
        : "r"(addr));
}
#endif  // TC_OK

static __device__ __forceinline__ uint64_t smem_desc(uint32_t addr) {
    const uint64_t base = (2ull << 61) | (1ull << 46) | (64ull << 32) | (1ull << 16);
    return base | ((addr >> 4) & 0x3FFF);
}
// idesc: kind::f16, dtype=F32, a=b=BF16, M=128, N=64
#define IDESC64 0x8100490u

// ---------------------------------------------------------------------------
// Projection GEMM: g_xall[m, 3072] = x @ Ucat^T + b   (~1 ms)
// ---------------------------------------------------------------------------
__global__ __launch_bounds__(256) void proj_kernel(
    const float* __restrict__ A,
    const float* __restrict__ Uc, const float* __restrict__ Ua,
    const float* __restrict__ Uh,
    const float* __restrict__ bc, const float* __restrict__ ba)
{
    __shared__ float As[8][128];
    __shared__ float Bs[8][128];

    const int tid = threadIdx.x;
    const int m0  = blockIdx.y * 128;
    const int n0  = blockIdx.x * 128;
    const int sel = n0 >> 10;
    const float* __restrict__ U = (sel == 0) ? Uc : (sel == 1) ? Ua : Uh;
    const int noff = n0 & (H_ - 1);

    const int lrow = tid >> 1;
    const int lk4  = (tid & 1) * 4;

    const float* Aptr = A + (size_t)(m0 + lrow) * I_ + lk4;
    const float* Uptr = U + (size_t)(noff + lrow) * I_ + lk4;

    const int tx = tid & 15;
    const int ty = tid >> 4;

    float acc[8][8];
    #pragma unroll
    for (int i = 0; i < 8; i++)
        #pragma unroll
        for (int j = 0; j < 8; j++) acc[i][j] = 0.0f;

    for (int k0 = 0; k0 < I_; k0 += 8) {
        float4 av = *(const float4*)(Aptr + k0);
        float4 uv = *(const float4*)(Uptr + k0);
        __syncthreads();
        As[lk4 + 0][lrow] = av.x; As[lk4 + 1][lrow] = av.y;
        As[lk4 + 2][lrow] = av.z; As[lk4 + 3][lrow] = av.w;
        Bs[lk4 + 0][lrow] = uv.x; Bs[lk4 + 1][lrow] = uv.y;
        Bs[lk4 + 2][lrow] = uv.z; Bs[lk4 + 3][lrow] = uv.w;
        __syncthreads();

        #pragma unroll
        for (int k = 0; k < 8; k++) {
            float4 a0 = *(const float4*)&As[k][ty * 4];
            float4 a1 = *(const float4*)&As[k][64 + ty * 4];
            float4 b0 = *(const float4*)&Bs[k][tx * 4];
            float4 b1 = *(const float4*)&Bs[k][64 + tx * 4];
            float a[8] = {a0.x, a0.y, a0.z, a0.w, a1.x, a1.y, a1.z, a1.w};
            float b[8] = {b0.x, b0.y, b0.z, b0.w, b1.x, b1.y, b1.z, b1.w};
            #pragma unroll
            for (int i = 0; i < 8; i++)
                #pragma unroll
                for (int j = 0; j < 8; j++) acc[i][j] += a[i] * b[j];
        }
    }

    #pragma unroll
    for (int ii = 0; ii < 2; ii++) {
        #pragma unroll
        for (int i = 0; i < 4; i++) {
            int r = ii * 64 + ty * 4 + i;
            float* crow = &g_xall[(size_t)(m0 + r) * N3 + n0];
            #pragma unroll
            for (int jj = 0; jj < 2; jj++) {
                int cb = jj * 64 + tx * 4;
                float4 bv;
                if (sel == 0)      bv = *(const float4*)&bc[noff + cb];
                else if (sel == 1) bv = *(const float4*)&ba[noff + cb];
                else               bv = make_float4(0.f, 0.f, 0.f, 0.f);
                int ai = ii * 4 + i;
                float4 o;
                o.x = acc[ai][jj * 4 + 0] + bv.x;
                o.y = acc[ai][jj * 4 + 1] + bv.y;
                o.z = acc[ai][jj * 4 + 2] + bv.z;
                o.w = acc[ai][jj * 4 + 3] + bv.w;
                *(float4*)&crow[cb] = o;
            }
        }
    }
}

// ---------------------------------------------------------------------------
// Pack W_c, W_a into interleaved bf16 hi/lo Wcat (32-column blocks):
// row r: j=r>>6, m=(r>>5)&1, i=r&31 -> W_m[32j+i].
// ---------------------------------------------------------------------------
__global__ __launch_bounds__(256) void pack_w(const float* __restrict__ Wc,
                                              const float* __restrict__ Wa)
{
    int idx = blockIdx.x * 256 + threadIdx.x;
    int r  = idx >> 8;
    int c4 = (idx & 255) * 4;
    int j = r >> 6, m = (r >> 5) & 1, i = r & 31;
    const float* src = (m ? Wa : Wc) + (size_t)(32 * j + i) * H_ + c4;
    float4 v = *(const float4*)src;

    __nv_bfloat16 h0 = __float2bfloat16(v.x), h1 = __float2bfloat16(v.y);
    __nv_bfloat16 h2 = __float2bfloat16(v.z), h3 = __float2bfloat16(v.w);
    __nv_bfloat16 l0 = __float2bfloat16(v.x - __bfloat162float(h0));
    __nv_bfloat16 l1 = __float2bfloat16(v.y - __bfloat162float(h1));
    __nv_bfloat16 l2 = __float2bfloat16(v.z - __bfloat162float(h2));
    __nv_bfloat16 l3 = __float2bfloat16(v.w - __bfloat162float(h3));

    __nv_bfloat16* dh = g_Whi + (size_t)r * H_ + c4;
    __nv_bfloat16* dl = g_Wlo + (size_t)r * H_ + c4;
    __nv_bfloat162 p;
    p.x = h0; p.y = h1; *(__nv_bfloat162*)(dh + 0) = p;
    p.x = h2; p.y = h3; *(__nv_bfloat162*)(dh + 2) = p;
    p.x = l0; p.y = l1; *(__nv_bfloat162*)(dl + 0) = p;
    p.x = l2; p.y = l3; *(__nv_bfloat162*)(dl + 2) = p;
}

// h0 fp32 -> hi/lo bf16 into state buffer 0
__global__ __launch_bounds__(256) void conv_h0(const float* __restrict__ h)
{
    int idx = blockIdx.x * 256 + threadIdx.x;
    float4 v = *(const float4*)(h + (size_t)idx * 4);
    __nv_bfloat16 h0 = __float2bfloat16(v.x), h1 = __float2bfloat16(v.y);
    __nv_bfloat16 h2 = __float2bfloat16(v.z), h3 = __float2bfloat16(v.w);
    __nv_bfloat16 l0 = __float2bfloat16(v.x - __bfloat162float(h0));
    __nv_bfloat16 l1 = __float2bfloat16(v.y - __bfloat162float(h1));
    __nv_bfloat16 l2 = __float2bfloat16(v.z - __bfloat162float(h2));
    __nv_bfloat16 l3 = __float2bfloat16(v.w - __bfloat162float(h3));
    __nv_bfloat16* dh = g_hhi[0] + (size_t)idx * 4;
    __nv_bfloat16* dl = g_hlo[0] + (size_t)idx * 4;
    __nv_bfloat162 p;
    p.x = h0; p.y = h1; *(__nv_bfloat162*)(dh + 0) = p;
    p.x = h2; p.y = h3; *(__nv_bfloat162*)(dh + 2) = p;
    p.x = l0; p.y = l1; *(__nv_bfloat162*)(dl + 0) = p;
    p.x = l2; p.y = l3; *(__nv_bfloat162*)(dl + 2) = p;
}

// ---------------------------------------------------------------------------
// Step kernel with TMA mainloop: M=128 x N=64; K=1024 in 16 chunks of 64.
// Single thread drives 4-stage TMA+mbarrier pipeline and MMA dispatch.
// Grid (32,2)=64 CTAs x 256 threads.
// ---------------------------------------------------------------------------
#define KC       64
#define A_B      16384                 // 128 rows x 128B
#define B_B      8192                  // 64 rows x 128B
#define STG_B    (2 * A_B + 2 * B_B)   // 48 KB
#define OFF_AHI  0
#define OFF_ALO  16384
#define OFF_BHI  32768
#define OFF_BLO  40960
#define NSTG     4
#define DYN_SMEM (NSTG * STG_B + 1024)
#define TX_BYTES 49152u

__device__ __forceinline__ float fast_sig(float x) {
    return __fdividef(1.0f, 1.0f + __expf(-x));
}
__device__ __forceinline__ float fast_tanh(float x) {
    float e = __expf(2.0f * x);
    return 1.0f - __fdividef(2.0f, e + 1.0f);
}
__device__ __forceinline__ float nbrc_el(float cpre, float apre, float xh, float hp)
{
    float c = fast_sig(cpre);
    float a = 1.0f + fast_tanh(apre);
    return c * hp + (1.0f - c) * fast_tanh(xh + a * hp);
}

__device__ __forceinline__ void store_hilo(__nv_bfloat16* dh, __nv_bfloat16* dl, float4 o)
{
    __nv_bfloat16 h0 = __float2bfloat16(o.x), h1 = __float2bfloat16(o.y);
    __nv_bfloat16 h2 = __float2bfloat16(o.z), h3 = __float2bfloat16(o.w);
    __nv_bfloat16 l0 = __float2bfloat16(o.x - __bfloat162float(h0));
    __nv_bfloat16 l1 = __float2bfloat16(o.y - __bfloat162float(h1));
    __nv_bfloat16 l2 = __float2bfloat16(o.z - __bfloat162float(h2));
    __nv_bfloat16 l3 = __float2bfloat16(o.w - __bfloat162float(h3));
    __nv_bfloat162 p;
    p.x = h0; p.y = h1; *(__nv_bfloat162*)(dh + 0) = p;
    p.x = h2; p.y = h3; *(__nv_bfloat162*)(dh + 2) = p;
    p.x = l0; p.y = l1; *(__nv_bfloat162*)(dl + 0) = p;
    p.x = l2; p.y = l3; *(__nv_bfloat162*)(dl + 2) = p;
}

__global__ __launch_bounds__(256, 1) void step_mma(
    int t, int sbuf,
    const float* __restrict__ hprev,
    float* __restrict__ hout,
    const __grid_constant__ CUtensorMap tmAhi,
    const __grid_constant__ CUtensorMap tmAlo,
    const __grid_constant__ CUtensorMap tmBhi,
    const __grid_constant__ CUtensorMap tmBlo)
{
#if TC_OK
    extern __shared__ char dynraw[];
    __shared__ uint32_t s_tmem[1];
    __shared__ __align__(8) uint64_t s_full[NSTG];
    __shared__ __align__(8) uint64_t s_free[NSTG];

    const int tid = threadIdx.x;
    const int wid = tid >> 5;
    const int m0  = blockIdx.y * 128;
    const int n0  = blockIdx.x * 64;
    const int jh  = blockIdx.x * 32;

    const uint32_t rawb = smem_u32(dynraw);
    const uint32_t dynb = (rawb + 1023u) & ~1023u;   // SW128: 1024B-aligned base

    __nv_bfloat16* __restrict__ nhhi = g_hhi[sbuf ^ 1];
    __nv_bfloat16* __restrict__ nhlo = g_hlo[sbuf ^ 1];

    uint32_t mbF[NSTG], mbE[NSTG];
    #pragma unroll
    for (int i = 0; i < NSTG; i++) {
        mbF[i] = smem_u32(&s_full[i]);
        mbE[i] = smem_u32(&s_free[i]);
    }

    if (wid == 0) tmem_alloc(smem_u32(s_tmem), 64);
    if (tid == 0) {
        #pragma unroll
        for (int i = 0; i < NSTG; i++) { mbar_init(mbF[i], 1); mbar_init(mbE[i], 1); }
    }

    // ---- early epilogue operand prefetch (cold xall stream) ----
    const int lane = tid & 31;
    const int sub  = wid & 3;
    const int cg   = wid >> 2;
    const int be   = m0 + sub * 32 + lane;
    const int hb   = jh + cg * 16;

    float4 pxc[4], pxa[4], pxh[4], php[4];
    {
        const float* xrow = g_xall + (size_t)t * B_ * N3 + (size_t)be * N3;
        #pragma unroll
        for (int i = 0; i < 4; i++) {
            pxc[i] = __ldcs((const float4*)(xrow + hb + 4 * i));
            pxa[i] = __ldcs((const float4*)(xrow + 1024 + hb + 4 * i));
            pxh[i] = __ldcs((const float4*)(xrow + 2048 + hb + 4 * i));
            php[i] = *(const float4*)(hprev + (size_t)be * H_ + hb + 4 * i);
        }
    }

    __syncthreads();
    const uint32_t tmem = s_tmem[0];

    // ---- single-thread TMA + MMA pipeline ----
    if (tid == 0) {
        auto issue = [&](int c) {
            const int s = c & (NSTG - 1);
            const int k0 = c * KC;
            const uint32_t sg = dynb + s * STG_B;
            mbar_expect_tx(mbF[s], TX_BYTES);
            tma2d(sg + OFF_AHI, &tmAhi, k0, m0, mbF[s]);
            tma2d(sg + OFF_ALO, &tmAlo, k0, m0, mbF[s]);
            tma2d(sg + OFF_BHI, &tmBhi, k0, n0, mbF[s]);
            tma2d(sg + OFF_BLO, &tmBlo, k0, n0, mbF[s]);
        };

        issue(0); issue(1); issue(2);

        uint32_t ffp = 0, efp = 0;
        #pragma unroll 1
        for (int c = 0; c < 16; c++) {
            const int s = c & (NSTG - 1);
            mbar_wait(mbF[s], (ffp >> s) & 1u);
            ffp ^= 1u << s;

            const uint32_t sg = dynb + s * STG_B;
            uint64_t dah = smem_desc(sg + OFF_AHI);
            uint64_t dal = smem_desc(sg + OFF_ALO);
            uint64_t dbh = smem_desc(sg + OFF_BHI);
            uint64_t dbl = smem_desc(sg + OFF_BLO);
            #pragma unroll
            for (int st = 0; st < 4; st++) {
                mma_f16_ss(tmem, dah + 2 * st, dbh + 2 * st, IDESC64, (c | st) != 0);
                mma_f16_ss(tmem, dah + 2 * st, dbl + 2 * st, IDESC64, 1);
                mma_f16_ss(tmem, dal + 2 * st, dbh + 2 * st, IDESC64, 1);
            }
            tc_commit(mbE[s]);

            if (c < 13) {
                const int ns = (c + 3) & (NSTG - 1);
                if (c >= 1) {                      // stage ns freed by MMA of chunk c-1
                    mbar_wait(mbE[ns], (efp >> ns) & 1u);
                    efp ^= 1u << ns;
                }
                issue(c + 3);
            }
        }
        mbar_wait(mbE[3], (efp >> 3) & 1u);        // chunk 15's MMA done
    }

    __syncthreads();
    tc_fence_after();

    // ---- epilogue: GEMM results from TMEM; x/h operands already in regs ----
    {
        uint32_t dc[16], da[16];
        tmem_ld16(dc, tmem + cg * 16);
        tmem_ld16(da, tmem + 32 + cg * 16);
        tc_wait_ld();
        tc_fence_before();

        #pragma unroll
        for (int j = 0; j < 4; j++) {
            int hc = hb + 4 * j;
            int i  = 4 * j;
            float4 o;
            o.x = nbrc_el(pxc[j].x + __uint_as_float(dc[i + 0]), pxa[j].x + __uint_as_float(da[i + 0]), pxh[j].x, php[j].x);
            o.y = nbrc_el(pxc[j].y + __uint_as_float(dc[i + 1]), pxa[j].y + __uint_as_float(da[i + 1]), pxh[j].y, php[j].y);
            o.z = nbrc_el(pxc[j].z + __uint_as_float(dc[i + 2]), pxa[j].z + __uint_as_float(da[i + 2]), pxh[j].z, php[j].z);
            o.w = nbrc_el(pxc[j].w + __uint_as_float(dc[i + 3]), pxa[j].w + __uint_as_float(da[i + 3]), pxh[j].w, php[j].w);
            *(float4*)(hout + (size_t)be * H_ + hc) = o;
            store_hilo(nhhi + (size_t)be * H_ + hc, nhlo + (size_t)be * H_ + hc, o);
        }
    }

    __syncthreads();
    if (tid == 0) {
        #pragma unroll
        for (int i = 0; i < NSTG; i++) { mbar_inval(mbF[i]); mbar_inval(mbE[i]); }
    }
    __syncthreads();
    if (wid == 0) {
        tmem_relinquish();
        tmem_dealloc(tmem, 64);
    }
#else
    // ---- SIMT fallback (plain compute_103 pass; never selected on GB300) ----
    const int tid = threadIdx.x;
    const int m0  = blockIdx.y * 128;
    const int n0  = blockIdx.x * 64;
    const int jh  = blockIdx.x * 32;
    const int sbx = sbuf ^ 1;

    const int b    = m0 + (tid >> 1);
    const int half = tid & 1;

    const float* xrow = g_xall + (size_t)t * B_ * N3 + (size_t)b * N3;
    for (int jj = 0; jj < 16; jj++) {
        const int j    = half * 16 + jj;
        const int hc   = jh + j;
        const int rowc = n0 + j;
        const int rowa = n0 + 32 + j;
        float sc = 0.f, sa = 0.f;
        const float* hp = hprev + (size_t)b * H_;
        for (int k = 0; k < H_; k++) {
            float wc = __bfloat162float(g_Whi[(size_t)rowc * H_ + k]) +
                       __bfloat162float(g_Wlo[(size_t)rowc * H_ + k]);
            float wa = __bfloat162float(g_Whi[(size_t)rowa * H_ + k]) +
                       __bfloat162float(g_Wlo[(size_t)rowa * H_ + k]);
            sc += hp[k] * wc;
            sa += hp[k] * wa;
        }
        float hpv = hprev[(size_t)b * H_ + hc];
        float o = nbrc_el(xrow[hc] + sc, xrow[1024 + hc] + sa, xrow[2048 + hc], hpv);
        hout[(size_t)b * H_ + hc] = o;
        __nv_bfloat16 hi = __float2bfloat16(o);
        __nv_bfloat16 lo = __float2bfloat16(o - __bfloat162float(hi));
        g_hhi[sbx][(size_t)b * H_ + hc] = hi;
        g_hlo[sbx][(size_t)b * H_ + hc] = lo;
    }
#endif
}

// ---------------------------------------------------------------------------
// Host: tensor-map construction (once) + launch sequence.
// ---------------------------------------------------------------------------
typedef CUresult (*tm_encode_fn)(
    CUtensorMap*, CUtensorMapDataType, cuuint32_t, void*,
    const cuuint64_t*, const cuuint64_t*, const cuuint32_t*, const cuuint32_t*,
    CUtensorMapInterleave, CUtensorMapSwizzle, CUtensorMapL2promotion,
    CUtensorMapFloatOOBfill);

static CUtensorMap s_tmA[2][2];   // [sbuf][hi=0,lo=1]
static CUtensorMap s_tmW[2];      // [hi,lo]
static bool s_tm_init = false;

static void init_tensor_maps()
{
    void* fn = nullptr;
    cudaDriverEntryPointQueryResult qr;
    cudaGetDriverEntryPointByVersion("cuTensorMapEncodeTiled", &fn, 12000,
                                     cudaEnableDefault, &qr);
    tm_encode_fn enc = (tm_encode_fn)fn;

    void *phhi, *phlo, *pwhi, *pwlo;
    cudaGetSymbolAddress(&phhi, g_hhi);
    cudaGetSymbolAddress(&phlo, g_hlo);
    cudaGetSymbolAddress(&pwhi, g_Whi);
    cudaGetSymbolAddress(&pwlo, g_Wlo);

    const cuuint64_t dimsA[2] = {H_, B_};
    const cuuint64_t strA[1]  = {H_ * 2};
    const cuuint32_t boxA[2]  = {64, 128};
    const cuuint64_t dimsW[2] = {H_, NW};
    const cuuint64_t strW[1]  = {H_ * 2};
    const cuuint32_t boxW[2]  = {64, 64};
    const cuuint32_t es[2]    = {1, 1};
    const size_t hbytes = (size_t)B_ * H_ * sizeof(__nv_bfloat16);

    for (int b = 0; b < 2; b++) {
        enc(&s_tmA[b][0], CU_TENSOR_MAP_DATA_TYPE_BFLOAT16, 2,
            (char*)phhi + (size_t)b * hbytes, dimsA, strA, boxA, es,
            CU_TENSOR_MAP_INTERLEAVE_NONE, CU_TENSOR_MAP_SWIZZLE_128B,
            CU_TENSOR_MAP_L2_PROMOTION_L2_128B, CU_TENSOR_MAP_FLOAT_OOB_FILL_NONE);
        enc(&s_tmA[b][1], CU_TENSOR_MAP_DATA_TYPE_BFLOAT16, 2,
            (char*)phlo + (size_t)b * hbytes, dimsA, strA, boxA, es,
            CU_TENSOR_MAP_INTERLEAVE_NONE, CU_TENSOR_MAP_SWIZZLE_128B,
            CU_TENSOR_MAP_L2_PROMOTION_L2_128B, CU_TENSOR_MAP_FLOAT_OOB_FILL_NONE);
    }
    enc(&s_tmW[0], CU_TENSOR_MAP_DATA_TYPE_BFLOAT16, 2, pwhi, dimsW, strW, boxW, es,
        CU_TENSOR_MAP_INTERLEAVE_NONE, CU_TENSOR_MAP_SWIZZLE_128B,
        CU_TENSOR_MAP_L2_PROMOTION_L2_128B, CU_TENSOR_MAP_FLOAT_OOB_FILL_NONE);
    enc(&s_tmW[1], CU_TENSOR_MAP_DATA_TYPE_BFLOAT16, 2, pwlo, dimsW, strW, boxW, es,
        CU_TENSOR_MAP_INTERLEAVE_NONE, CU_TENSOR_MAP_SWIZZLE_128B,
        CU_TENSOR_MAP_L2_PROMOTION_L2_128B, CU_TENSOR_MAP_FLOAT_OOB_FILL_NONE);
}

extern "C" void kernel_launch(void* const* d_in, const int* in_sizes, int n_in,
                              void* d_out, int out_size)
{
    const float* x   = (const float*)d_in[0];
    const float* h0i = (const float*)d_in[1];
    const float* Uc  = (const float*)d_in[2];
    const float* Wc  = (const float*)d_in[3];
    const float* bc  = (const float*)d_in[4];
    const float* Ua  = (const float*)d_in[5];
    const float* Wa  = (const float*)d_in[6];
    const float* ba  = (const float*)d_in[7];
    const float* Uh  = (const float*)d_in[8];
    float* out = (float*)d_out;

    if (!s_tm_init) {
        cudaFuncSetAttribute(step_mma, cudaFuncAttributeMaxDynamicSharedMemorySize, DYN_SMEM);
        init_tensor_maps();
        s_tm_init = true;
    }

    pack_w<<<2048, 256>>>(Wc, Wa);
    conv_h0<<<256, 256>>>(h0i);

    dim3 pgrid(N3 / 128, M_ / 128);
    proj_kernel<<<pgrid, 256>>>(x, Uc, Ua, Uh, bc, ba);

    dim3 sgrid(32, 2);
    for (int t = 0; t < T_; t++) {
        const int sb = t & 1;
        const float* hp = (t == 0) ? h0i : out + (size_t)(t - 1) * B_ * H_;
        step_mma<<<sgrid, 256, DYN_SMEM>>>(t, sb, hp, out + (size_t)t * B_ * H_,
                                           s_tmA[sb][0], s_tmA[sb][1],
                                           s_tmW[0], s_tmW[1]);
    }

    cudaMemcpyAsync(out + (size_t)T_ * B_ * H_,
                    out + (size_t)(T_ - 1) * B_ * H_,
                    (size_t)B_ * H_ * sizeof(float),
                    cudaMemcpyDeviceToDevice);
}

// round 16
// speedup vs baseline: 1.1231x; 1.1231x over previous
#include <cuda_runtime.h>
#include <cuda.h>
#include <cuda_bf16.h>
#include <math.h>
#include <stdint.h>

#define T_  512
#define B_  256
#define I_  512
#define H_  1024
#define N3  3072
#define M_  (T_ * B_)
#define NW  2048                     // rows of interleaved Wcat (c||a per 16-col block)

#if !defined(__CUDA_ARCH__) || defined(__CUDA_ARCH_FEAT_SM103_ALL) || defined(__CUDA_ARCH_FEAT_SM100_ALL) || defined(__CUDA_ARCH_FEAT_SM101_ALL)
#define TC_OK 1
#else
#define TC_OK 0
#endif

// ---------------- device scratch -----------------------
__device__ float         g_xall[(size_t)M_ * N3];
__device__ __nv_bfloat16 g_Whi[(size_t)NW * H_];
__device__ __nv_bfloat16 g_Wlo[(size_t)NW * H_];
__device__ __nv_bfloat16 g_hhi[2][(size_t)B_ * H_];
__device__ __nv_bfloat16 g_hlo[2][(size_t)B_ * H_];

// ---------------- PTX helpers ----------------------------------------------
__device__ __forceinline__ uint32_t smem_u32(const void* p) {
    uint32_t a;
    asm("{ .reg .u64 t; cvta.to.shared.u64 t, %1; cvt.u32.u64 %0, t; }" : "=r"(a) : "l"(p));
    return a;
}
__device__ __forceinline__ void mbar_init(uint32_t m, uint32_t cnt) {
    asm volatile("mbarrier.init.shared.b64 [%0], %1;" :: "r"(m), "r"(cnt) : "memory");
}
__device__ __forceinline__ void mbar_inval(uint32_t m) {
    asm volatile("mbarrier.inval.shared.b64 [%0];" :: "r"(m) : "memory");
}
__device__ __forceinline__ void mbar_wait(uint32_t m, uint32_t parity) {
    asm volatile(
        "{\n\t.reg .pred P;\n"
        "W%=:\n\t"
        "mbarrier.try_wait.parity.acquire.cta.shared::cta.b64 P, [%0], %1, 0x989680;\n\t"
        "@P bra D%=;\n\t"
        "bra W%=;\n"
        "D%=:\n\t}"
        :: "r"(m), "r"(parity) : "memory");
}
__device__ __forceinline__ void mbar_expect_tx(uint32_t m, uint32_t bytes) {
    asm volatile("mbarrier.arrive.expect_tx.shared.b64 _, [%0], %1;"
                 :: "r"(m), "r"(bytes) : "memory");
}
__device__ __forceinline__ void tma2d(uint32_t smem, const CUtensorMap* map,
                                      int x, int y, uint32_t mbar) {
    asm volatile(
        "cp.async.bulk.tensor.2d.shared::cta.global.tile.mbarrier::complete_tx::bytes "
        "[%0], [%1, {%2, %3}], [%4];"
        :: "r"(smem), "l"(map), "r"(x), "r"(y), "r"(mbar) : "memory");
}

#if TC_OK
__device__ __forceinline__ void tmem_alloc(uint32_t dst_smem, uint32_t ncols) {
    asm volatile("tcgen05.alloc.cta_group::1.sync.aligned.shared::cta.b32 [%0], %1;"
                 :: "r"(dst_smem), "r"(ncols) : "memory");
}
__device__ __forceinline__ void tmem_dealloc(uint32_t tmem, uint32_t ncols) {
    asm volatile("tcgen05.dealloc.cta_group::1.sync.aligned.b32 %0, %1;" :: "r"(tmem), "r"(ncols));
}
__device__ __forceinline__ void tmem_relinquish() {
    asm volatile("tcgen05.relinquish_alloc_permit.cta_group::1.sync.aligned;");
}
__device__ __forceinline__ void tc_commit(uint32_t m) {
    asm volatile("tcgen05.commit.cta_group::1.mbarrier::arrive::one.shared::cluster.b64 [%0];"
                 :: "r"(m) : "memory");
}
__device__ __forceinline__ void tc_fence_after() {
    asm volatile("tcgen05.fence::after_thread_sync;" ::: "memory");
}
__device__ __forceinline__ void tc_fence_before() {
    asm volatile("tcgen05.fence::before_thread_sync;" ::: "memory");
}
__device__ __forceinline__ void tc_wait_ld() {
    asm volatile("tcgen05.wait::ld.sync.aligned;" ::: "memory");
}
__device__ __forceinline__ void mma_f16_ss(uint32_t d, uint64_t ad, uint64_t bd,
                                           uint32_t idesc, uint32_t en) {
    asm volatile(
        "{\n\t.reg .pred p;\n\t"
        "setp.ne.u32 p, %4, 0;\n\t"
        "tcgen05.mma.cta_group::1.kind::f16 [%0], %1, %2, %3, {%5, %5, %5, %5}, p;\n\t}"
        :: "r"(d), "l"(ad), "l"(bd), "r"(idesc), "r"(en), "r"(0u) : "memory");
}
__device__ __forceinline__ void tmem_ld8(uint32_t* r, uint32_t addr) {
    asm volatile(
        "tcgen05.ld.sync.aligned.32x32b.x8.b32 "
        "{%0, %1, %2, %3, %4, %5, %6, %7}, [%8];"
        : "=r"(r[0]), "=r"(r[1]), "=r"(r[2]), "=r"(r[3]),
          "=r"(r[4]), "=r"(r[5]), "=r"(r[6]), "=r"(r[7])
        : "r"(addr));
}
#endif  // TC_OK

static __device__ __forceinline__ uint64_t smem_desc(uint32_t addr) {
    const uint64_t base = (2ull << 61) | (1ull << 46) | (64ull << 32) | (1ull << 16);
    return base | ((addr >> 4) & 0x3FFF);
}
// idesc: kind::f16, dtype=F32, a=b=BF16, M=128, N=32 (HW-validated in test_mma.cu)
#define IDESC32 0x8080490u

// ---------------------------------------------------------------------------
// Projection GEMM: g_xall[m, 3072] = x @ Ucat^T + b   (~1 ms)
// ---------------------------------------------------------------------------
__global__ __launch_bounds__(256) void proj_kernel(
    const float* __restrict__ A,
    const float* __restrict__ Uc, const float* __restrict__ Ua,
    const float* __restrict__ Uh,
    const float* __restrict__ bc, const float* __restrict__ ba)
{
    __shared__ float As[8][128];
    __shared__ float Bs[8][128];

    const int tid = threadIdx.x;
    const int m0  = blockIdx.y * 128;
    const int n0  = blockIdx.x * 128;
    const int sel = n0 >> 10;
    const float* __restrict__ U = (sel == 0) ? Uc : (sel == 1) ? Ua : Uh;
    const int noff = n0 & (H_ - 1);

    const int lrow = tid >> 1;
    const int lk4  = (tid & 1) * 4;

    const float* Aptr = A + (size_t)(m0 + lrow) * I_ + lk4;
    const float* Uptr = U + (size_t)(noff + lrow) * I_ + lk4;

    const int tx = tid & 15;
    const int ty = tid >> 4;

    float acc[8][8];
    #pragma unroll
    for (int i = 0; i < 8; i++)
        #pragma unroll
        for (int j = 0; j < 8; j++) acc[i][j] = 0.0f;

    for (int k0 = 0; k0 < I_; k0 += 8) {
        float4 av = *(const float4*)(Aptr + k0);
        float4 uv = *(const float4*)(Uptr + k0);
        __syncthreads();
        As[lk4 + 0][lrow] = av.x; As[lk4 + 1][lrow] = av.y;
        As[lk4 + 2][lrow] = av.z; As[lk4 + 3][lrow] = av.w;
        Bs[lk4 + 0][lrow] = uv.x; Bs[lk4 + 1][lrow] = uv.y;
        Bs[lk4 + 2][lrow] = uv.z; Bs[lk4 + 3][lrow] = uv.w;
        __syncthreads();

        #pragma unroll
        for (int k = 0; k < 8; k++) {
            float4 a0 = *(const float4*)&As[k][ty * 4];
            float4 a1 = *(const float4*)&As[k][64 + ty * 4];
            float4 b0 = *(const float4*)&Bs[k][tx * 4];
            float4 b1 = *(const float4*)&Bs[k][64 + tx * 4];
            float a[8] = {a0.x, a0.y, a0.z, a0.w, a1.x, a1.y, a1.z, a1.w};
            float b[8] = {b0.x, b0.y, b0.z, b0.w, b1.x, b1.y, b1.z, b1.w};
            #pragma unroll
            for (int i = 0; i < 8; i++)
                #pragma unroll
                for (int j = 0; j < 8; j++) acc[i][j] += a[i] * b[j];
        }
    }

    #pragma unroll
    for (int ii = 0; ii < 2; ii++) {
        #pragma unroll
        for (int i = 0; i < 4; i++) {
            int r = ii * 64 + ty * 4 + i;
            float* crow = &g_xall[(size_t)(m0 + r) * N3 + n0];
            #pragma unroll
            for (int jj = 0; jj < 2; jj++) {
                int cb = jj * 64 + tx * 4;
                float4 bv;
                if (sel == 0)      bv = *(const float4*)&bc[noff + cb];
                else if (sel == 1) bv = *(const float4*)&ba[noff + cb];
                else               bv = make_float4(0.f, 0.f, 0.f, 0.f);
                int ai = ii * 4 + i;
                float4 o;
                o.x = acc[ai][jj * 4 + 0] + bv.x;
                o.y = acc[ai][jj * 4 + 1] + bv.y;
                o.z = acc[ai][jj * 4 + 2] + bv.z;
                o.w = acc[ai][jj * 4 + 3] + bv.w;
                *(float4*)&crow[cb] = o;
            }
        }
    }
}

// ---------------------------------------------------------------------------
// Pack W_c, W_a into interleaved bf16 hi/lo Wcat (16-column blocks for N=32
// tiles): row r = 32j + 16m + i  ->  W_m[16j + i],  j=r>>5, m=(r>>4)&1, i=r&15.
// ---------------------------------------------------------------------------
__global__ __launch_bounds__(256) void pack_w(const float* __restrict__ Wc,
                                              const float* __restrict__ Wa)
{
    int idx = blockIdx.x * 256 + threadIdx.x;
    int r  = idx >> 8;
    int c4 = (idx & 255) * 4;
    int j = r >> 5, m = (r >> 4) & 1, i = r & 15;
    const float* src = (m ? Wa : Wc) + (size_t)(16 * j + i) * H_ + c4;
    float4 v = *(const float4*)src;

    __nv_bfloat16 h0 = __float2bfloat16(v.x), h1 = __float2bfloat16(v.y);
    __nv_bfloat16 h2 = __float2bfloat16(v.z), h3 = __float2bfloat16(v.w);
    __nv_bfloat16 l0 = __float2bfloat16(v.x - __bfloat162float(h0));
    __nv_bfloat16 l1 = __float2bfloat16(v.y - __bfloat162float(h1));
    __nv_bfloat16 l2 = __float2bfloat16(v.z - __bfloat162float(h2));
    __nv_bfloat16 l3 = __float2bfloat16(v.w - __bfloat162float(h3));

    __nv_bfloat16* dh = g_Whi + (size_t)r * H_ + c4;
    __nv_bfloat16* dl = g_Wlo + (size_t)r * H_ + c4;
    __nv_bfloat162 p;
    p.x = h0; p.y = h1; *(__nv_bfloat162*)(dh + 0) = p;
    p.x = h2; p.y = h3; *(__nv_bfloat162*)(dh + 2) = p;
    p.x = l0; p.y = l1; *(__nv_bfloat162*)(dl + 0) = p;
    p.x = l2; p.y = l3; *(__nv_bfloat162*)(dl + 2) = p;
}

// h0 fp32 -> hi/lo bf16 into state buffer 0
__global__ __launch_bounds__(256) void conv_h0(const float* __restrict__ h)
{
    int idx = blockIdx.x * 256 + threadIdx.x;
    float4 v = *(const float4*)(h + (size_t)idx * 4);
    __nv_bfloat16 h0 = __float2bfloat16(v.x), h1 = __float2bfloat16(v.y);
    __nv_bfloat16 h2 = __float2bfloat16(v.z), h3 = __float2bfloat16(v.w);
    __nv_bfloat16 l0 = __float2bfloat16(v.x - __bfloat162float(h0));
    __nv_bfloat16 l1 = __float2bfloat16(v.y - __bfloat162float(h1));
    __nv_bfloat16 l2 = __float2bfloat16(v.z - __bfloat162float(h2));
    __nv_bfloat16 l3 = __float2bfloat16(v.w - __bfloat162float(h3));
    __nv_bfloat16* dh = g_hhi[0] + (size_t)idx * 4;
    __nv_bfloat16* dl = g_hlo[0] + (size_t)idx * 4;
    __nv_bfloat162 p;
    p.x = h0; p.y = h1; *(__nv_bfloat162*)(dh + 0) = p;
    p.x = h2; p.y = h3; *(__nv_bfloat162*)(dh + 2) = p;
    p.x = l0; p.y = l1; *(__nv_bfloat162*)(dl + 0) = p;
    p.x = l2; p.y = l3; *(__nv_bfloat162*)(dl + 2) = p;
}

// ---------------------------------------------------------------------------
// Step kernel: M=128 (batch) x N=32 (16 h-cols x {c,a}); K=1024 in 16 chunks
// of 64. TMA 4-stage pipeline driven by thread 0. Grid (64,2)=128 CTAs.
// ---------------------------------------------------------------------------
#define KC       64
#define A_B      16384                 // 128 rows x 128B
#define B_B      4096                  // 32 rows x 128B
#define STG_B    (2 * A_B + 2 * B_B)   // 40 KB
#define OFF_AHI  0
#define OFF_ALO  16384
#define OFF_BHI  32768
#define OFF_BLO  36864
#define NSTG     4
#define DYN_SMEM (NSTG * STG_B + 1024)
#define TX_BYTES 40960u

__device__ __forceinline__ float fast_sig(float x) {
    return __fdividef(1.0f, 1.0f + __expf(-x));
}
__device__ __forceinline__ float fast_tanh(float x) {
    float e = __expf(2.0f * x);
    return 1.0f - __fdividef(2.0f, e + 1.0f);
}
__device__ __forceinline__ float nbrc_el(float cpre, float apre, float xh, float hp)
{
    float c = fast_sig(cpre);
    float a = 1.0f + fast_tanh(apre);
    return c * hp + (1.0f - c) * fast_tanh(xh + a * hp);
}

__device__ __forceinline__ void store_hilo(__nv_bfloat16* dh, __nv_bfloat16* dl, float4 o)
{
    __nv_bfloat16 h0 = __float2bfloat16(o.x), h1 = __float2bfloat16(o.y);
    __nv_bfloat16 h2 = __float2bfloat16(o.z), h3 = __float2bfloat16(o.w);
    __nv_bfloat16 l0 = __float2bfloat16(o.x - __bfloat162float(h0));
    __nv_bfloat16 l1 = __float2bfloat16(o.y - __bfloat162float(h1));
    __nv_bfloat16 l2 = __float2bfloat16(o.z - __bfloat162float(h2));
    __nv_bfloat16 l3 = __float2bfloat16(o.w - __bfloat162float(h3));
    __nv_bfloat162 p;
    p.x = h0; p.y = h1; *(__nv_bfloat162*)(dh + 0) = p;
    p.x = h2; p.y = h3; *(__nv_bfloat162*)(dh + 2) = p;
    p.x = l0; p.y = l1; *(__nv_bfloat162*)(dl + 0) = p;
    p.x = l2; p.y = l3; *(__nv_bfloat162*)(dl + 2) = p;
}

__global__ __launch_bounds__(256, 1) void step_mma(
    int t, int sbuf,
    const float* __restrict__ hprev,
    float* __restrict__ hout,
    const __grid_constant__ CUtensorMap tmAhi,
    const __grid_constant__ CUtensorMap tmAlo,
    const __grid_constant__ CUtensorMap tmBhi,
    const __grid_constant__ CUtensorMap tmBlo)
{
#if TC_OK
    extern __shared__ char dynraw[];
    __shared__ uint32_t s_tmem[1];
    __shared__ __align__(8) uint64_t s_full[NSTG];
    __shared__ __align__(8) uint64_t s_free[NSTG];

    const int tid = threadIdx.x;
    const int wid = tid >> 5;
    const int m0  = blockIdx.y * 128;
    const int n0  = blockIdx.x * 32;    // Wcat row tile
    const int jh  = blockIdx.x * 16;    // h-column base

    const uint32_t rawb = smem_u32(dynraw);
    const uint32_t dynb = (rawb + 1023u) & ~1023u;   // SW128: 1024B-aligned base

    __nv_bfloat16* __restrict__ nhhi = g_hhi[sbuf ^ 1];
    __nv_bfloat16* __restrict__ nhlo = g_hlo[sbuf ^ 1];

    uint32_t mbF[NSTG], mbE[NSTG];
    #pragma unroll
    for (int i = 0; i < NSTG; i++) {
        mbF[i] = smem_u32(&s_full[i]);
        mbE[i] = smem_u32(&s_free[i]);
    }

    if (wid == 0) tmem_alloc(smem_u32(s_tmem), 32);
    if (tid == 0) {
        #pragma unroll
        for (int i = 0; i < NSTG; i++) { mbar_init(mbF[i], 1); mbar_init(mbE[i], 1); }
    }

    // ---- early epilogue operand prefetch (cold xall stream) ----
    const int lane = tid & 31;
    const int sub  = wid & 3;
    const int cg   = wid >> 2;                  // 0 or 1 (8 h-cols each)
    const int be   = m0 + sub * 32 + lane;
    const int hb   = jh + cg * 8;

    float4 pxc[2], pxa[2], pxh[2], php[2];
    {
        const float* xrow = g_xall + (size_t)t * B_ * N3 + (size_t)be * N3;
        #pragma unroll
        for (int i = 0; i < 2; i++) {
            pxc[i] = __ldcs((const float4*)(xrow + hb + 4 * i));
            pxa[i] = __ldcs((const float4*)(xrow + 1024 + hb + 4 * i));
            pxh[i] = __ldcs((const float4*)(xrow + 2048 + hb + 4 * i));
            php[i] = *(const float4*)(hprev + (size_t)be * H_ + hb + 4 * i);
        }
    }

    __syncthreads();
    const uint32_t tmem = s_tmem[0];

    // ---- single-thread TMA + MMA pipeline ----
    if (tid == 0) {
        auto issue = [&](int c) {
            const int s = c & (NSTG - 1);
            const int k0 = c * KC;
            const uint32_t sg = dynb + s * STG_B;
            mbar_expect_tx(mbF[s], TX_BYTES);
            tma2d(sg + OFF_AHI, &tmAhi, k0, m0, mbF[s]);
            tma2d(sg + OFF_ALO, &tmAlo, k0, m0, mbF[s]);
            tma2d(sg + OFF_BHI, &tmBhi, k0, n0, mbF[s]);
            tma2d(sg + OFF_BLO, &tmBlo, k0, n0, mbF[s]);
        };

        issue(0); issue(1); issue(2);

        uint32_t ffp = 0, efp = 0;
        #pragma unroll 1
        for (int c = 0; c < 16; c++) {
            const int s = c & (NSTG - 1);
            mbar_wait(mbF[s], (ffp >> s) & 1u);
            ffp ^= 1u << s;

            const uint32_t sg = dynb + s * STG_B;
            uint64_t dah = smem_desc(sg + OFF_AHI);
            uint64_t dal = smem_desc(sg + OFF_ALO);
            uint64_t dbh = smem_desc(sg + OFF_BHI);
            uint64_t dbl = smem_desc(sg + OFF_BLO);
            #pragma unroll
            for (int st = 0; st < 4; st++) {
                mma_f16_ss(tmem, dah + 2 * st, dbh + 2 * st, IDESC32, (c | st) != 0);
                mma_f16_ss(tmem, dah + 2 * st, dbl + 2 * st, IDESC32, 1);
                mma_f16_ss(tmem, dal + 2 * st, dbh + 2 * st, IDESC32, 1);
            }
            tc_commit(mbE[s]);

            if (c < 13) {
                const int ns = (c + 3) & (NSTG - 1);
                if (c >= 1) {                      // stage ns freed by MMA of chunk c-1
                    mbar_wait(mbE[ns], (efp >> ns) & 1u);
                    efp ^= 1u << ns;
                }
                issue(c + 3);
            }
        }
        mbar_wait(mbE[3], (efp >> 3) & 1u);        // chunk 15's MMA done
    }

    __syncthreads();
    tc_fence_after();

    // ---- epilogue: GEMM results from TMEM; x/h operands already in regs ----
    {
        uint32_t dc[8], da[8];
        tmem_ld8(dc, tmem + cg * 8);               // c preacts (cols 0..15)
        tmem_ld8(da, tmem + 16 + cg * 8);          // a preacts (cols 16..31)
        tc_wait_ld();
        tc_fence_before();

        #pragma unroll
        for (int j = 0; j < 2; j++) {
            int hc = hb + 4 * j;
            int i  = 4 * j;
            float4 o;
            o.x = nbrc_el(pxc[j].x + __uint_as_float(dc[i + 0]), pxa[j].x + __uint_as_float(da[i + 0]), pxh[j].x, php[j].x);
            o.y = nbrc_el(pxc[j].y + __uint_as_float(dc[i + 1]), pxa[j].y + __uint_as_float(da[i + 1]), pxh[j].y, php[j].y);
            o.z = nbrc_el(pxc[j].z + __uint_as_float(dc[i + 2]), pxa[j].z + __uint_as_float(da[i + 2]), pxh[j].z, php[j].z);
            o.w = nbrc_el(pxc[j].w + __uint_as_float(dc[i + 3]), pxa[j].w + __uint_as_float(da[i + 3]), pxh[j].w, php[j].w);
            *(float4*)(hout + (size_t)be * H_ + hc) = o;
            store_hilo(nhhi + (size_t)be * H_ + hc, nhlo + (size_t)be * H_ + hc, o);
        }
    }

    __syncthreads();
    if (tid == 0) {
        #pragma unroll
        for (int i = 0; i < NSTG; i++) { mbar_inval(mbF[i]); mbar_inval(mbE[i]); }
    }
    __syncthreads();
    if (wid == 0) {
        tmem_relinquish();
        tmem_dealloc(tmem, 32);
    }
#else
    // ---- SIMT fallback (plain compute_103 pass; never selected on GB300) ----
    const int tid = threadIdx.x;
    const int m0  = blockIdx.y * 128;
    const int n0  = blockIdx.x * 32;
    const int jh  = blockIdx.x * 16;
    const int sbx = sbuf ^ 1;

    const int b    = m0 + (tid >> 1);
    const int half = tid & 1;

    const float* xrow = g_xall + (size_t)t * B_ * N3 + (size_t)b * N3;
    for (int jj = 0; jj < 8; jj++) {
        const int j    = half * 8 + jj;
        const int hc   = jh + j;
        const int rowc = n0 + j;
        const int rowa = n0 + 16 + j;
        float sc = 0.f, sa = 0.f;
        const float* hp = hprev + (size_t)b * H_;
        for (int k = 0; k < H_; k++) {
            float wc = __bfloat162float(g_Whi[(size_t)rowc * H_ + k]) +
                       __bfloat162float(g_Wlo[(size_t)rowc * H_ + k]);
            float wa = __bfloat162float(g_Whi[(size_t)rowa * H_ + k]) +
                       __bfloat162float(g_Wlo[(size_t)rowa * H_ + k]);
            sc += hp[k] * wc;
            sa += hp[k] * wa;
        }
        float hpv = hprev[(size_t)b * H_ + hc];
        float o = nbrc_el(xrow[hc] + sc, xrow[1024 + hc] + sa, xrow[2048 + hc], hpv);
        hout[(size_t)b * H_ + hc] = o;
        __nv_bfloat16 hi = __float2bfloat16(o);
        __nv_bfloat16 lo = __float2bfloat16(o - __bfloat162float(hi));
        g_hhi[sbx][(size_t)b * H_ + hc] = hi;
        g_hlo[sbx][(size_t)b * H_ + hc] = lo;
    }
#endif
}

// ---------------------------------------------------------------------------
// Host: tensor-map construction (once) + launch sequence.
// ---------------------------------------------------------------------------
typedef CUresult (*tm_encode_fn)(
    CUtensorMap*, CUtensorMapDataType, cuuint32_t, void*,
    const cuuint64_t*, const cuuint64_t*, const cuuint32_t*, const cuuint32_t*,
    CUtensorMapInterleave, CUtensorMapSwizzle, CUtensorMapL2promotion,
    CUtensorMapFloatOOBfill);

static CUtensorMap s_tmA[2][2];   // [sbuf][hi=0,lo=1]
static CUtensorMap s_tmW[2];      // [hi,lo]
static bool s_tm_init = false;

static void init_tensor_maps()
{
    void* fn = nullptr;
    cudaDriverEntryPointQueryResult qr;
    cudaGetDriverEntryPointByVersion("cuTensorMapEncodeTiled", &fn, 12000,
                                     cudaEnableDefault, &qr);
    tm_encode_fn enc = (tm_encode_fn)fn;

    void *phhi, *phlo, *pwhi, *pwlo;
    cudaGetSymbolAddress(&phhi, g_hhi);
    cudaGetSymbolAddress(&phlo, g_hlo);
    cudaGetSymbolAddress(&pwhi, g_Whi);
    cudaGetSymbolAddress(&pwlo, g_Wlo);

    const cuuint64_t dimsA[2] = {H_, B_};
    const cuuint64_t strA[1]  = {H_ * 2};
    const cuuint32_t boxA[2]  = {64, 128};
    const cuuint64_t dimsW[2] = {H_, NW};
    const cuuint64_t strW[1]  = {H_ * 2};
    const cuuint32_t boxW[2]  = {64, 32};
    const cuuint32_t es[2]    = {1, 1};
    const size_t hbytes = (size_t)B_ * H_ * sizeof(__nv_bfloat16);

    for (int b = 0; b < 2; b++) {
        enc(&s_tmA[b][0], CU_TENSOR_MAP_DATA_TYPE_BFLOAT16, 2,
            (char*)phhi + (size_t)b * hbytes, dimsA, strA, boxA, es,
            CU_TENSOR_MAP_INTERLEAVE_NONE, CU_TENSOR_MAP_SWIZZLE_128B,
            CU_TENSOR_MAP_L2_PROMOTION_L2_128B, CU_TENSOR_MAP_FLOAT_OOB_FILL_NONE);
        enc(&s_tmA[b][1], CU_TENSOR_MAP_DATA_TYPE_BFLOAT16, 2,
            (char*)phlo + (size_t)b * hbytes, dimsA, strA, boxA, es,
            CU_TENSOR_MAP_INTERLEAVE_NONE, CU_TENSOR_MAP_SWIZZLE_128B,
            CU_TENSOR_MAP_L2_PROMOTION_L2_128B, CU_TENSOR_MAP_FLOAT_OOB_FILL_NONE);
    }
    enc(&s_tmW[0], CU_TENSOR_MAP_DATA_TYPE_BFLOAT16, 2, pwhi, dimsW, strW, boxW, es,
        CU_TENSOR_MAP_INTERLEAVE_NONE, CU_TENSOR_MAP_SWIZZLE_128B,
        CU_TENSOR_MAP_L2_PROMOTION_L2_128B, CU_TENSOR_MAP_FLOAT_OOB_FILL_NONE);
    enc(&s_tmW[1], CU_TENSOR_MAP_DATA_TYPE_BFLOAT16, 2, pwlo, dimsW, strW, boxW, es,
        CU_TENSOR_MAP_INTERLEAVE_NONE, CU_TENSOR_MAP_SWIZZLE_128B,
        CU_TENSOR_MAP_L2_PROMOTION_L2_128B, CU_TENSOR_MAP_FLOAT_OOB_FILL_NONE);
}

extern "C" void kernel_launch(void* const* d_in, const int* in_sizes, int n_in,
                              void* d_out, int out_size)
{
    const float* x   = (const float*)d_in[0];
    const float* h0i = (const float*)d_in[1];
    const float* Uc  = (const float*)d_in[2];
    const float* Wc  = (const float*)d_in[3];
    const float* bc  = (const float*)d_in[4];
    const float* Ua  = (const float*)d_in[5];
    const float* Wa  = (const float*)d_in[6];
    const float* ba  = (const float*)d_in[7];
    const float* Uh  = (const float*)d_in[8];
    float* out = (float*)d_out;

    if (!s_tm_init) {
        cudaFuncSetAttribute(step_mma, cudaFuncAttributeMaxDynamicSharedMemorySize, DYN_SMEM);
        init_tensor_maps();
        s_tm_init = true;
    }

    pack_w<<<2048, 256>>>(Wc, Wa);
    conv_h0<<<256, 256>>>(h0i);

    dim3 pgrid(N3 / 128, M_ / 128);
    proj_kernel<<<pgrid, 256>>>(x, Uc, Ua, Uh, bc, ba);

    dim3 sgrid(64, 2);
    for (int t = 0; t < T_; t++) {
        const int sb = t & 1;
        const float* hp = (t == 0) ? h0i : out + (size_t)(t - 1) * B_ * H_;
        step_mma<<<sgrid, 256, DYN_SMEM>>>(t, sb, hp, out + (size_t)t * B_ * H_,
                                           s_tmA[sb][0], s_tmA[sb][1],
                                           s_tmW[0], s_tmW[1]);
    }

    cudaMemcpyAsync(out + (size_t)T_ * B_ * H_,
                    out + (size_t)(T_ - 1) * B_ * H_,
                    (size_t)B_ * H_ * sizeof(float),
                    cudaMemcpyDeviceToDevice);
}